// round 1
// baseline (speedup 1.0000x reference)
#include <cuda_runtime.h>
#include <cuda_bf16.h>
#include <math.h>

// Problem constants (fixed shapes from reference setup_inputs)
#define B_  8
#define L_  4096
#define D_  384
#define NH_ 8
#define NP_ 4
#define HD_ 48           // D_/NH_
#define GRID_ 64         // h = w = sqrt(L_) = 64
#define M_  (B_ * L_)    // 32768 rows

// ---------------- scratch (no cudaMalloc allowed) ----------------
__device__ float g_v[(size_t)M_ * D_];       // value @ Wv + bv        (50.3 MB)
__device__ float g_offwt[(size_t)M_ * 96];   // [off(64) | wt(32)]     (12.6 MB)
__device__ float g_attn[(size_t)M_ * D_];    // sampled+aggregated     (50.3 MB)

// ---------------- SGEMM: C[M,N] = A[M,K] @ W[K,N] + bias[N] ----------------
// BM=128, BN=128, BK=8, TM=TN=8, 256 threads. Shapes here are exact multiples,
// no bounds checks needed (M=32768, N=384=3*128, K=384=48*8).
__global__ __launch_bounds__(256, 2)
void sgemm_bias_kernel(const float* __restrict__ A,
                       const float* __restrict__ W,
                       const float* __restrict__ bias,
                       float* __restrict__ C,
                       int M, int N, int K) {
    constexpr int BM = 128, BN = 128, BK = 8, TM = 8, TN = 8;
    __shared__ float As[BK][BM];
    __shared__ float Bs[BK][BN];

    const int tid = threadIdx.x;
    const int m0 = blockIdx.y * BM;
    const int n0 = blockIdx.x * BN;

    const int tx = tid % (BN / TN);   // 0..15
    const int ty = tid / (BN / TN);   // 0..15

    // A tile load mapping: 128 rows x 8 cols = 256 float4 (2 per row)
    const int aRow = tid >> 1;            // 0..127
    const int aCol = (tid & 1) * 4;       // 0 or 4
    // B tile load mapping: 8 rows x 128 cols = 256 float4
    const int bRow = tid >> 5;            // 0..7
    const int bCol = (tid & 31) * 4;      // 0..124

    float acc[TM][TN];
    #pragma unroll
    for (int i = 0; i < TM; i++)
        #pragma unroll
        for (int j = 0; j < TN; j++) acc[i][j] = 0.f;

    const float* Aptr = A + (size_t)(m0 + aRow) * K + aCol;
    const float* Wptr = W + (size_t)bRow * N + n0 + bCol;

    for (int k0 = 0; k0 < K; k0 += BK) {
        float4 av = *reinterpret_cast<const float4*>(Aptr + k0);
        As[aCol + 0][aRow] = av.x;
        As[aCol + 1][aRow] = av.y;
        As[aCol + 2][aRow] = av.z;
        As[aCol + 3][aRow] = av.w;
        float4 bv4 = *reinterpret_cast<const float4*>(Wptr + (size_t)k0 * N);
        *reinterpret_cast<float4*>(&Bs[bRow][bCol]) = bv4;
        __syncthreads();

        #pragma unroll
        for (int k = 0; k < BK; k++) {
            float ra[TM], rb[TN];
            #pragma unroll
            for (int i = 0; i < TM; i++) ra[i] = As[k][ty * TM + i];
            #pragma unroll
            for (int j = 0; j < TN; j++) rb[j] = Bs[k][tx * TN + j];
            #pragma unroll
            for (int i = 0; i < TM; i++)
                #pragma unroll
                for (int j = 0; j < TN; j++) acc[i][j] += ra[i] * rb[j];
        }
        __syncthreads();
    }

    #pragma unroll
    for (int i = 0; i < TM; i++) {
        float* crow = C + (size_t)(m0 + ty * TM + i) * N + n0 + tx * TN;
        #pragma unroll
        for (int j = 0; j < TN; j += 4) {
            float4 o;
            o.x = acc[i][j + 0] + bias[n0 + tx * TN + j + 0];
            o.y = acc[i][j + 1] + bias[n0 + tx * TN + j + 1];
            o.z = acc[i][j + 2] + bias[n0 + tx * TN + j + 2];
            o.w = acc[i][j + 3] + bias[n0 + tx * TN + j + 3];
            *reinterpret_cast<float4*>(crow + j) = o;
        }
    }
}

// ---------------- offset + weight projection ----------------
// One block per row (b,l). out[row, 0:64]  = query_row @ Woff + boff
//                          out[row, 64:96] = query_row @ Wwt  + bwt
__global__ __launch_bounds__(96)
void proj_offwt_kernel(const float* __restrict__ query,
                       const float* __restrict__ Woff, const float* __restrict__ boff,
                       const float* __restrict__ Wwt,  const float* __restrict__ bwt,
                       float* __restrict__ out) {
    __shared__ float qs[D_];
    const int row = blockIdx.x;
    const int t = threadIdx.x;   // 0..95

    const float* qrow = query + (size_t)row * D_;
    #pragma unroll
    for (int i = t; i < D_; i += 96) qs[i] = qrow[i];
    __syncthreads();

    const float* Wcol;
    float bias;
    int stride;
    if (t < 64) { Wcol = Woff + t;        bias = boff[t];      stride = 64; }
    else        { Wcol = Wwt + (t - 64);  bias = bwt[t - 64];  stride = 32; }

    float acc = bias;
    #pragma unroll 8
    for (int k = 0; k < D_; k++) acc += qs[k] * Wcol[(size_t)k * stride];

    out[(size_t)row * 96 + t] = acc;
}

// ---------------- sampling: softmax + bilinear gather + point aggregation ----------------
// One block per (b,l). 384 threads; thread t handles output channel d=t
// (head = t/48, within-head = t%48).
__global__ __launch_bounds__(384)
void sample_kernel(const float* __restrict__ v,       // g_v [B,L,D]
                   const float* __restrict__ offwt,   // [M,96]
                   float* __restrict__ attn) {        // [B,L,D]
    __shared__ float row[96];
    __shared__ float sw[NH_][NP_];
    __shared__ int   sidx[NH_][NP_][4];
    __shared__ float swg[NH_][NP_][4];

    const int bl = blockIdx.x;           // 0..32767
    const int b = bl >> 12;
    const int l = bl & (L_ - 1);
    const int t = threadIdx.x;

    if (t < 96) row[t] = offwt[(size_t)bl * 96 + t];
    __syncthreads();

    if (t < NH_) {
        // softmax over the 4 point logits of head t
        float lg[NP_];
        float m = -1e30f;
        #pragma unroll
        for (int p = 0; p < NP_; p++) { lg[p] = row[64 + t * NP_ + p]; m = fmaxf(m, lg[p]); }
        float s = 0.f;
        #pragma unroll
        for (int p = 0; p < NP_; p++) { lg[p] = __expf(lg[p] - m); s += lg[p]; }
        float inv = 1.f / s;
        #pragma unroll
        for (int p = 0; p < NP_; p++) sw[t][p] = lg[p] * inv;
    }
    __syncthreads();

    if (t < NH_ * NP_) {
        const int hh = t >> 2, p = t & 3;
        const float off0 = row[hh * (NP_ * 2) + p * 2 + 0];
        const float off1 = row[hh * (NP_ * 2) + p * 2 + 1];
        // ref grid: ref[...,0] = x over cols, ref[...,1] = y over rows
        const float gx = (float)(l & (GRID_ - 1)) * (1.f / (GRID_ - 1));
        const float gy = (float)(l >> 6)          * (1.f / (GRID_ - 1));
        // faithful to source: component 0 -> row coord, component 1 -> col coord
        const float ph = fminf(fmaxf(gx + off0, 0.f), 1.f) * (float)(GRID_ - 1);
        const float pw = fminf(fmaxf(gy + off1, 0.f), 1.f) * (float)(GRID_ - 1);
        const float y0f = floorf(ph), x0f = floorf(pw);
        const float wy = ph - y0f,    wx = pw - x0f;
        const int y0 = (int)y0f, x0 = (int)x0f;
        const int y1 = min(y0 + 1, GRID_ - 1);
        const int x1 = min(x0 + 1, GRID_ - 1);
        const float s = sw[hh][p];
        sidx[hh][p][0] = y0 * GRID_ + x0;  swg[hh][p][0] = s * (1.f - wy) * (1.f - wx);
        sidx[hh][p][1] = y0 * GRID_ + x1;  swg[hh][p][1] = s * (1.f - wy) * wx;
        sidx[hh][p][2] = y1 * GRID_ + x0;  swg[hh][p][2] = s * wy * (1.f - wx);
        sidx[hh][p][3] = y1 * GRID_ + x1;  swg[hh][p][3] = s * wy * wx;
    }
    __syncthreads();

    const int hh = t / HD_;
    const int dh = t % HD_;
    const float* vb = v + (size_t)b * L_ * D_ + hh * HD_ + dh;

    float acc = 0.f;
    #pragma unroll
    for (int p = 0; p < NP_; p++) {
        #pragma unroll
        for (int c = 0; c < 4; c++) {
            acc += swg[hh][p][c] * vb[(size_t)sidx[hh][p][c] * D_];
        }
    }
    attn[(size_t)bl * D_ + t] = acc;
}

// ---------------- launch ----------------
extern "C" void kernel_launch(void* const* d_in, const int* in_sizes, int n_in,
                              void* d_out, int out_size) {
    const float* query = (const float*)d_in[0];
    // d_in[1] = key   (dead)
    const float* value = (const float*)d_in[2];
    // d_in[3] = Wq, d_in[4] = bq, d_in[5] = Wk, d_in[6] = bk   (dead)
    const float* Wv   = (const float*)d_in[7];
    const float* bv   = (const float*)d_in[8];
    const float* Woff = (const float*)d_in[9];
    const float* boff = (const float*)d_in[10];
    const float* Wwt  = (const float*)d_in[11];
    const float* bwt  = (const float*)d_in[12];
    const float* Wo   = (const float*)d_in[13];
    const float* bo   = (const float*)d_in[14];
    float* out = (float*)d_out;

    float *gv, *gow, *gat;
    cudaGetSymbolAddress((void**)&gv,  g_v);
    cudaGetSymbolAddress((void**)&gow, g_offwt);
    cudaGetSymbolAddress((void**)&gat, g_attn);

    // 1) v = value @ Wv + bv
    {
        dim3 grid(D_ / 128, M_ / 128);
        sgemm_bias_kernel<<<grid, 256>>>(value, Wv, bv, gv, M_, D_, D_);
    }
    // 2) off/wt projection from query
    proj_offwt_kernel<<<M_, 96>>>(query, Woff, boff, Wwt, bwt, gow);
    // 3) softmax + bilinear sampling + point aggregation
    sample_kernel<<<M_, 384>>>(gv, gow, gat);
    // 4) out = attn @ Wo + bo
    {
        dim3 grid(D_ / 128, M_ / 128);
        sgemm_bias_kernel<<<grid, 256>>>(gat, Wo, bo, out, M_, D_, D_);
    }
}

// round 2
// speedup vs baseline: 1.0969x; 1.0969x over previous
#include <cuda_runtime.h>
#include <cuda_bf16.h>
#include <math.h>
#include <stdint.h>

// Problem constants (fixed shapes from reference setup_inputs)
#define B_  8
#define L_  4096
#define D_  384
#define NH_ 8
#define NP_ 4
#define HD_ 48           // D_/NH_
#define GRID_ 64         // h = w = sqrt(L_) = 64
#define M_  (B_ * L_)    // 32768 rows

// ---------------- scratch (no cudaMalloc allowed) ----------------
__device__ float g_v[(size_t)M_ * D_];       // value @ Wv + bv        (50.3 MB)
__device__ float g_offwt[(size_t)M_ * 96];   // [off(64) | wt(32)]     (12.6 MB)
__device__ float g_attn[(size_t)M_ * D_];    // sampled+aggregated     (50.3 MB)

// =====================================================================
// Tensor-core GEMM (3xTF32): C[M,N] = A[M,K] @ W[K,N] + bias[N]
// BM=128, BN=128, BK=32, 256 threads (8 warps, 2x4), warp tile 64x32.
// A is split into tf32 hi/lo during the gmem->smem stage; inner loop is
// LDS + mma.sync.m16n8k8.tf32 only. Accuracy ~ fp32 (3-term product).
// =====================================================================

#define BM_ 128
#define BN_ 128
#define BK_ 32
#define ASTR 36          // smem row stride (floats) for A tiles (conflict-free frag loads)
#define BSTR 136         // smem row stride (floats) for B tiles
#define A_WORDS (BM_ * ASTR)          // 4608
#define B_WORDS (BK_ * BSTR)          // 4352
#define SMEM_WORDS (2 * A_WORDS + 2 * B_WORDS)   // 17920 words = 71680 B

__device__ __forceinline__ uint32_t f2tf32(float f) {
    uint32_t u;
    asm("cvt.rna.tf32.f32 %0, %1;" : "=r"(u) : "f"(f));
    return u;
}

__device__ __forceinline__ void split_tf32(float f, uint32_t& hi, uint32_t& lo) {
    hi = f2tf32(f);
    float r = f - __uint_as_float(hi);
    lo = f2tf32(r);
}

__device__ __forceinline__ void mma_tf32(float c[4], uint32_t a0, uint32_t a1,
                                         uint32_t a2, uint32_t a3,
                                         uint32_t b0, uint32_t b1) {
    asm volatile(
        "mma.sync.aligned.m16n8k8.row.col.f32.tf32.tf32.f32 "
        "{%0,%1,%2,%3}, {%4,%5,%6,%7}, {%8,%9}, {%0,%1,%2,%3};"
        : "+f"(c[0]), "+f"(c[1]), "+f"(c[2]), "+f"(c[3])
        : "r"(a0), "r"(a1), "r"(a2), "r"(a3), "r"(b0), "r"(b1));
}

__global__ __launch_bounds__(256)
void gemm_tf32x3_kernel(const float* __restrict__ A,
                        const float* __restrict__ W,
                        const float* __restrict__ bias,
                        float* __restrict__ C,
                        int M, int N, int K) {
    extern __shared__ uint32_t smem[];
    uint32_t* Ahi = smem;
    uint32_t* Alo = smem + A_WORDS;
    uint32_t* Bhi = smem + 2 * A_WORDS;
    uint32_t* Blo = smem + 2 * A_WORDS + B_WORDS;

    const int tid  = threadIdx.x;
    const int lane = tid & 31;
    const int warp = tid >> 5;
    const int m0 = blockIdx.y * BM_;
    const int n0 = blockIdx.x * BN_;

    const int warp_m = warp >> 2;      // 0..1
    const int warp_n = warp & 3;       // 0..3
    const int mBase = warp_m * 64;
    const int nBase = warp_n * 32;
    const int qr = lane >> 2;          // 0..7
    const int qc = lane & 3;           // 0..3

    float acc[4][4][4];
    #pragma unroll
    for (int i = 0; i < 4; i++)
        #pragma unroll
        for (int j = 0; j < 4; j++)
            #pragma unroll
            for (int r = 0; r < 4; r++) acc[i][j][r] = 0.f;

    for (int k0 = 0; k0 < K; k0 += BK_) {
        // ---- stage A tile (128x32): 1024 float4, 4 per thread ----
        #pragma unroll
        for (int i = 0; i < 4; i++) {
            int idx = tid + i * 256;
            int row = idx >> 3;
            int c4  = (idx & 7) * 4;
            float4 v = *reinterpret_cast<const float4*>(A + (size_t)(m0 + row) * K + k0 + c4);
            uint32_t h0, l0, h1, l1, h2, l2, h3, l3;
            split_tf32(v.x, h0, l0); split_tf32(v.y, h1, l1);
            split_tf32(v.z, h2, l2); split_tf32(v.w, h3, l3);
            uint32_t* ph = Ahi + row * ASTR + c4;
            uint32_t* pl = Alo + row * ASTR + c4;
            ph[0] = h0; ph[1] = h1; ph[2] = h2; ph[3] = h3;
            pl[0] = l0; pl[1] = l1; pl[2] = l2; pl[3] = l3;
        }
        // ---- stage B tile (32x128): 1024 float4, 4 per thread ----
        #pragma unroll
        for (int i = 0; i < 4; i++) {
            int idx = tid + i * 256;
            int row = idx >> 5;
            int c4  = (idx & 31) * 4;
            float4 v = *reinterpret_cast<const float4*>(W + (size_t)(k0 + row) * N + n0 + c4);
            uint32_t h0, l0, h1, l1, h2, l2, h3, l3;
            split_tf32(v.x, h0, l0); split_tf32(v.y, h1, l1);
            split_tf32(v.z, h2, l2); split_tf32(v.w, h3, l3);
            uint32_t* ph = Bhi + row * BSTR + c4;
            uint32_t* pl = Blo + row * BSTR + c4;
            ph[0] = h0; ph[1] = h1; ph[2] = h2; ph[3] = h3;
            pl[0] = l0; pl[1] = l1; pl[2] = l2; pl[3] = l3;
        }
        __syncthreads();

        #pragma unroll
        for (int ks = 0; ks < 4; ks++) {
            const int kk = ks * 8;
            // B fragments for the 4 n-tiles
            uint32_t bh0[4], bh1[4], bl0[4], bl1[4];
            #pragma unroll
            for (int nt = 0; nt < 4; nt++) {
                int col = nBase + nt * 8 + qr;
                int r0 = (kk + qc) * BSTR + col;
                int r1 = (kk + qc + 4) * BSTR + col;
                bh0[nt] = Bhi[r0]; bh1[nt] = Bhi[r1];
                bl0[nt] = Blo[r0]; bl1[nt] = Blo[r1];
            }
            #pragma unroll
            for (int mt = 0; mt < 4; mt++) {
                int row = mBase + mt * 16 + qr;
                int i00 = row * ASTR + kk + qc;
                int i10 = (row + 8) * ASTR + kk + qc;
                uint32_t ah0 = Ahi[i00], ah1 = Ahi[i10];
                uint32_t ah2 = Ahi[i00 + 4], ah3 = Ahi[i10 + 4];
                uint32_t al0 = Alo[i00], al1 = Alo[i10];
                uint32_t al2 = Alo[i00 + 4], al3 = Alo[i10 + 4];
                #pragma unroll
                for (int nt = 0; nt < 4; nt++) {
                    mma_tf32(acc[mt][nt], ah0, ah1, ah2, ah3, bl0[nt], bl1[nt]);
                    mma_tf32(acc[mt][nt], al0, al1, al2, al3, bh0[nt], bh1[nt]);
                    mma_tf32(acc[mt][nt], ah0, ah1, ah2, ah3, bh0[nt], bh1[nt]);
                }
            }
        }
        __syncthreads();
    }

    // ---- epilogue: add bias, write fp32 ----
    #pragma unroll
    for (int mt = 0; mt < 4; mt++) {
        int r0 = m0 + mBase + mt * 16 + qr;
        int r1 = r0 + 8;
        #pragma unroll
        for (int nt = 0; nt < 4; nt++) {
            int c0 = n0 + nBase + nt * 8 + 2 * qc;
            float b0 = bias[c0], b1 = bias[c0 + 1];
            float2 o0 = make_float2(acc[mt][nt][0] + b0, acc[mt][nt][1] + b1);
            float2 o1 = make_float2(acc[mt][nt][2] + b0, acc[mt][nt][3] + b1);
            *reinterpret_cast<float2*>(C + (size_t)r0 * N + c0) = o0;
            *reinterpret_cast<float2*>(C + (size_t)r1 * N + c0) = o1;
        }
    }
}

// ---------------- offset + weight projection (kept exact fp32) ----------------
__global__ __launch_bounds__(96)
void proj_offwt_kernel(const float* __restrict__ query,
                       const float* __restrict__ Woff, const float* __restrict__ boff,
                       const float* __restrict__ Wwt,  const float* __restrict__ bwt,
                       float* __restrict__ out) {
    __shared__ float qs[D_];
    const int row = blockIdx.x;
    const int t = threadIdx.x;   // 0..95

    const float* qrow = query + (size_t)row * D_;
    #pragma unroll
    for (int i = t; i < D_; i += 96) qs[i] = qrow[i];
    __syncthreads();

    const float* Wcol;
    float bias;
    int stride;
    if (t < 64) { Wcol = Woff + t;        bias = boff[t];      stride = 64; }
    else        { Wcol = Wwt + (t - 64);  bias = bwt[t - 64];  stride = 32; }

    float acc = bias;
    #pragma unroll 8
    for (int k = 0; k < D_; k++) acc += qs[k] * Wcol[(size_t)k * stride];

    out[(size_t)row * 96 + t] = acc;
}

// ---------------- sampling: softmax + bilinear gather + point aggregation ----------------
__global__ __launch_bounds__(384)
void sample_kernel(const float* __restrict__ v,       // g_v [B,L,D]
                   const float* __restrict__ offwt,   // [M,96]
                   float* __restrict__ attn) {        // [B,L,D]
    __shared__ float row[96];
    __shared__ float sw[NH_][NP_];
    __shared__ int   sidx[NH_][NP_][4];
    __shared__ float swg[NH_][NP_][4];

    const int bl = blockIdx.x;           // 0..32767
    const int b = bl >> 12;
    const int l = bl & (L_ - 1);
    const int t = threadIdx.x;

    if (t < 96) row[t] = offwt[(size_t)bl * 96 + t];
    __syncthreads();

    if (t < NH_) {
        float lg[NP_];
        float m = -1e30f;
        #pragma unroll
        for (int p = 0; p < NP_; p++) { lg[p] = row[64 + t * NP_ + p]; m = fmaxf(m, lg[p]); }
        float s = 0.f;
        #pragma unroll
        for (int p = 0; p < NP_; p++) { lg[p] = __expf(lg[p] - m); s += lg[p]; }
        float inv = 1.f / s;
        #pragma unroll
        for (int p = 0; p < NP_; p++) sw[t][p] = lg[p] * inv;
    }
    __syncthreads();

    if (t < NH_ * NP_) {
        const int hh = t >> 2, p = t & 3;
        const float off0 = row[hh * (NP_ * 2) + p * 2 + 0];
        const float off1 = row[hh * (NP_ * 2) + p * 2 + 1];
        const float gx = (float)(l & (GRID_ - 1)) * (1.f / (GRID_ - 1));
        const float gy = (float)(l >> 6)          * (1.f / (GRID_ - 1));
        const float ph = fminf(fmaxf(gx + off0, 0.f), 1.f) * (float)(GRID_ - 1);
        const float pw = fminf(fmaxf(gy + off1, 0.f), 1.f) * (float)(GRID_ - 1);
        const float y0f = floorf(ph), x0f = floorf(pw);
        const float wy = ph - y0f,    wx = pw - x0f;
        const int y0 = (int)y0f, x0 = (int)x0f;
        const int y1 = min(y0 + 1, GRID_ - 1);
        const int x1 = min(x0 + 1, GRID_ - 1);
        const float s = sw[hh][p];
        sidx[hh][p][0] = y0 * GRID_ + x0;  swg[hh][p][0] = s * (1.f - wy) * (1.f - wx);
        sidx[hh][p][1] = y0 * GRID_ + x1;  swg[hh][p][1] = s * (1.f - wy) * wx;
        sidx[hh][p][2] = y1 * GRID_ + x0;  swg[hh][p][2] = s * wy * (1.f - wx);
        sidx[hh][p][3] = y1 * GRID_ + x1;  swg[hh][p][3] = s * wy * wx;
    }
    __syncthreads();

    const int hh = t / HD_;
    const int dh = t % HD_;
    const float* vb = v + (size_t)b * L_ * D_ + hh * HD_ + dh;

    float acc = 0.f;
    #pragma unroll
    for (int p = 0; p < NP_; p++) {
        #pragma unroll
        for (int c = 0; c < 4; c++) {
            acc += swg[hh][p][c] * vb[(size_t)sidx[hh][p][c] * D_];
        }
    }
    attn[(size_t)bl * D_ + t] = acc;
}

// ---------------- launch ----------------
extern "C" void kernel_launch(void* const* d_in, const int* in_sizes, int n_in,
                              void* d_out, int out_size) {
    const float* query = (const float*)d_in[0];
    // d_in[1] = key   (dead)
    const float* value = (const float*)d_in[2];
    // d_in[3..6] = Wq, bq, Wk, bk (dead)
    const float* Wv   = (const float*)d_in[7];
    const float* bv   = (const float*)d_in[8];
    const float* Woff = (const float*)d_in[9];
    const float* boff = (const float*)d_in[10];
    const float* Wwt  = (const float*)d_in[11];
    const float* bwt  = (const float*)d_in[12];
    const float* Wo   = (const float*)d_in[13];
    const float* bo   = (const float*)d_in[14];
    float* out = (float*)d_out;

    float *gv, *gow, *gat;
    cudaGetSymbolAddress((void**)&gv,  g_v);
    cudaGetSymbolAddress((void**)&gow, g_offwt);
    cudaGetSymbolAddress((void**)&gat, g_attn);

    static bool attr_set = false;
    if (!attr_set) {
        cudaFuncSetAttribute(gemm_tf32x3_kernel,
                             cudaFuncAttributeMaxDynamicSharedMemorySize,
                             SMEM_WORDS * 4);
        attr_set = true;
    }

    const size_t smem_bytes = SMEM_WORDS * 4;

    // 1) v = value @ Wv + bv
    {
        dim3 grid(D_ / BN_, M_ / BM_);
        gemm_tf32x3_kernel<<<grid, 256, smem_bytes>>>(value, Wv, bv, gv, M_, D_, D_);
    }
    // 2) off/wt projection from query (exact fp32 — offsets are x63 error-amplified)
    proj_offwt_kernel<<<M_, 96>>>(query, Woff, boff, Wwt, bwt, gow);
    // 3) softmax + bilinear sampling + point aggregation
    sample_kernel<<<M_, 384>>>(gv, gow, gat);
    // 4) out = attn @ Wo + bo
    {
        dim3 grid(D_ / BN_, M_ / BM_);
        gemm_tf32x3_kernel<<<grid, 256, smem_bytes>>>(gat, Wo, bo, out, M_, D_, D_);
    }
}

// round 3
// speedup vs baseline: 2.1513x; 1.9611x over previous
#include <cuda_runtime.h>
#include <cuda_bf16.h>
#include <math.h>
#include <stdint.h>

// Problem constants (fixed shapes from reference setup_inputs)
#define B_  8
#define L_  4096
#define D_  384
#define NH_ 8
#define NP_ 4
#define HD_ 48           // D_/NH_
#define GRID_ 64         // h = w = sqrt(L_) = 64
#define M_  (B_ * L_)    // 32768 rows

// ---------------- scratch (no cudaMalloc allowed) ----------------
__device__ float g_v[(size_t)M_ * D_];        // value @ Wv + bv (fp32)
__device__ float g_offwt[(size_t)M_ * 96];    // [off(64) | wt(32)] fp32
__device__ float g_attn[(size_t)M_ * D_];     // sampled, tf32-rounded bit patterns
__device__ float g_acvt[(size_t)M_ * D_];     // value tf32-rounded
__device__ float g_wv32[D_ * D_];             // Wv tf32-rounded
__device__ float g_wo32[D_ * D_];             // Wo tf32-rounded

__device__ __forceinline__ uint32_t f2tf32(float f) {
    uint32_t u;
    asm("cvt.rna.tf32.f32 %0, %1;" : "=r"(u) : "f"(f));
    return u;
}

// ---------------- tf32 conversion pre-pass (float4 streaming) ----------------
__global__ __launch_bounds__(256)
void cvt_tf32_kernel(const float4* __restrict__ in, float4* __restrict__ out, int n4) {
    int i = blockIdx.x * blockDim.x + threadIdx.x;
    int stride = gridDim.x * blockDim.x;
    for (; i < n4; i += stride) {
        float4 v = in[i];
        float4 o;
        o.x = __uint_as_float(f2tf32(v.x));
        o.y = __uint_as_float(f2tf32(v.y));
        o.z = __uint_as_float(f2tf32(v.z));
        o.w = __uint_as_float(f2tf32(v.w));
        out[i] = o;
    }
}

// =====================================================================
// TF32 tensor-core GEMM with cp.async double buffering.
// C[M,N] = A[M,K] @ W[K,N] + bias[N].  A, W already tf32 bit patterns.
// BM=128, BN=128, BK=32, 256 threads (8 warps 2x4), warp tile 64x32.
// =====================================================================
#define BM_ 128
#define BN_ 128
#define BK_ 32
#define ASTR 36               // A smem row stride (words)
#define BSTR 136              // B smem row stride (words)
#define A_WORDS (BM_ * ASTR)  // 4608
#define B_WORDS (BK_ * BSTR)  // 4352
#define STAGE_WORDS (A_WORDS + B_WORDS)   // 8960 words = 35840 B
#define GEMM_SMEM_BYTES (2 * STAGE_WORDS * 4)

#define NK_ITERS (D_ / BK_)   // 12

__device__ __forceinline__ void cp_async16(uint32_t saddr, const void* gptr) {
    asm volatile("cp.async.cg.shared.global [%0], [%1], 16;\n" :: "r"(saddr), "l"(gptr));
}
__device__ __forceinline__ void cp_commit() {
    asm volatile("cp.async.commit_group;\n" ::: "memory");
}
template <int N>
__device__ __forceinline__ void cp_wait() {
    asm volatile("cp.async.wait_group %0;\n" :: "n"(N) : "memory");
}

__device__ __forceinline__ void mma_tf32(float c[4], uint32_t a0, uint32_t a1,
                                         uint32_t a2, uint32_t a3,
                                         uint32_t b0, uint32_t b1) {
    asm volatile(
        "mma.sync.aligned.m16n8k8.row.col.f32.tf32.tf32.f32 "
        "{%0,%1,%2,%3}, {%4,%5,%6,%7}, {%8,%9}, {%0,%1,%2,%3};"
        : "+f"(c[0]), "+f"(c[1]), "+f"(c[2]), "+f"(c[3])
        : "r"(a0), "r"(a1), "r"(a2), "r"(a3), "r"(b0), "r"(b1));
}

__global__ __launch_bounds__(256, 2)
void gemm_tf32_kernel(const float* __restrict__ A,
                      const float* __restrict__ W,
                      const float* __restrict__ bias,
                      float* __restrict__ C,
                      int M, int N, int K) {
    extern __shared__ uint32_t smem[];   // [2][STAGE_WORDS]

    const int tid  = threadIdx.x;
    const int lane = tid & 31;
    const int warp = tid >> 5;
    const int m0 = blockIdx.y * BM_;
    const int n0 = blockIdx.x * BN_;

    const int warp_m = warp >> 2;      // 0..1
    const int warp_n = warp & 3;       // 0..3
    const int mBase = warp_m * 64;
    const int nBase = warp_n * 32;
    const int qr = lane >> 2;          // 0..7
    const int qc = lane & 3;           // 0..3

    uint32_t smem_u32;
    {
        void* p = smem;
        smem_u32 = (uint32_t)__cvta_generic_to_shared(p);
    }

    // per-thread staging coordinates (A: 1024 16B chunks; B: 1024 16B chunks; 4 each)
    const int aRow0 = tid >> 3;           // chunk idx = tid + i*256 -> row = idx>>3
    const int aC16  = (tid & 7) * 16;     // byte offset within row (col*4B)
    const int bRow0 = tid >> 5;
    const int bC16  = (tid & 31) * 16;

    float acc[4][4][4];
    #pragma unroll
    for (int i = 0; i < 4; i++)
        #pragma unroll
        for (int j = 0; j < 4; j++)
            #pragma unroll
            for (int r = 0; r < 4; r++) acc[i][j][r] = 0.f;

    // ---- stage function (inlined twice) ----
    auto stage = [&](int k0, int buf) {
        uint32_t base = smem_u32 + buf * (STAGE_WORDS * 4);
        #pragma unroll
        for (int i = 0; i < 4; i++) {
            int arow = aRow0 + i * 32;                 // (tid + i*256)>>3
            uint32_t sa = base + arow * (ASTR * 4) + aC16;
            const float* ga = A + (size_t)(m0 + arow) * K + k0 + (aC16 >> 2);
            cp_async16(sa, ga);
            int brow = bRow0 + i * 8;                  // (tid + i*256)>>5
            uint32_t sb = base + (A_WORDS * 4) + brow * (BSTR * 4) + bC16;
            const float* gb = W + (size_t)(k0 + brow) * N + n0 + (bC16 >> 2);
            cp_async16(sb, gb);
        }
    };

    stage(0, 0);
    cp_commit();

    for (int it = 0; it < NK_ITERS; it++) {
        if (it + 1 < NK_ITERS) {
            stage((it + 1) * BK_, (it + 1) & 1);
            cp_commit();
            cp_wait<1>();
        } else {
            cp_wait<0>();
        }
        __syncthreads();

        const uint32_t* As = smem + (it & 1) * STAGE_WORDS;
        const uint32_t* Bs = As + A_WORDS;

        #pragma unroll
        for (int ks = 0; ks < 4; ks++) {
            const int kk = ks * 8;
            uint32_t b0[4], b1[4];
            #pragma unroll
            for (int nt = 0; nt < 4; nt++) {
                int col = nBase + nt * 8 + qr;
                b0[nt] = Bs[(kk + qc) * BSTR + col];
                b1[nt] = Bs[(kk + qc + 4) * BSTR + col];
            }
            #pragma unroll
            for (int mt = 0; mt < 4; mt++) {
                int row = mBase + mt * 16 + qr;
                int i00 = row * ASTR + kk + qc;
                int i10 = (row + 8) * ASTR + kk + qc;
                uint32_t a0 = As[i00], a1 = As[i10];
                uint32_t a2 = As[i00 + 4], a3 = As[i10 + 4];
                #pragma unroll
                for (int nt = 0; nt < 4; nt++) {
                    mma_tf32(acc[mt][nt], a0, a1, a2, a3, b0[nt], b1[nt]);
                }
            }
        }
        __syncthreads();
    }

    // ---- epilogue: add bias, write fp32 ----
    #pragma unroll
    for (int mt = 0; mt < 4; mt++) {
        int r0 = m0 + mBase + mt * 16 + qr;
        int r1 = r0 + 8;
        #pragma unroll
        for (int nt = 0; nt < 4; nt++) {
            int c0 = n0 + nBase + nt * 8 + 2 * qc;
            float bb0 = bias[c0], bb1 = bias[c0 + 1];
            float2 o0 = make_float2(acc[mt][nt][0] + bb0, acc[mt][nt][1] + bb1);
            float2 o1 = make_float2(acc[mt][nt][2] + bb0, acc[mt][nt][3] + bb1);
            *reinterpret_cast<float2*>(C + (size_t)r0 * N + c0) = o0;
            *reinterpret_cast<float2*>(C + (size_t)r1 * N + c0) = o1;
        }
    }
}

// ---------------- offset + weight projection (exact fp32, 8 rows/block) ----------------
#define PROJ_ROWS 8
__global__ __launch_bounds__(96)
void proj_offwt_kernel(const float* __restrict__ query,
                       const float* __restrict__ Woff, const float* __restrict__ boff,
                       const float* __restrict__ Wwt,  const float* __restrict__ bwt,
                       float* __restrict__ out) {
    __shared__ float qs[PROJ_ROWS][D_];
    const int r0 = blockIdx.x * PROJ_ROWS;
    const int t = threadIdx.x;   // 0..95

    // load 8 query rows (768 float4, 8 per thread)
    const float4* q4 = reinterpret_cast<const float4*>(query + (size_t)r0 * D_);
    float4* s4 = reinterpret_cast<float4*>(&qs[0][0]);
    #pragma unroll
    for (int i = 0; i < 8; i++) s4[t + i * 96] = q4[t + i * 96];
    __syncthreads();

    const float* Wcol;
    float bias;
    int stride;
    if (t < 64) { Wcol = Woff + t;        bias = boff[t];      stride = 64; }
    else        { Wcol = Wwt + (t - 64);  bias = bwt[t - 64];  stride = 32; }

    float acc[PROJ_ROWS];
    #pragma unroll
    for (int r = 0; r < PROJ_ROWS; r++) acc[r] = bias;

    for (int k = 0; k < D_; k += 4) {
        float w0 = Wcol[(size_t)(k + 0) * stride];
        float w1 = Wcol[(size_t)(k + 1) * stride];
        float w2 = Wcol[(size_t)(k + 2) * stride];
        float w3 = Wcol[(size_t)(k + 3) * stride];
        #pragma unroll
        for (int r = 0; r < PROJ_ROWS; r++) {
            float4 q = *reinterpret_cast<const float4*>(&qs[r][k]);
            acc[r] += q.x * w0;
            acc[r] += q.y * w1;
            acc[r] += q.z * w2;
            acc[r] += q.w * w3;
        }
    }

    #pragma unroll
    for (int r = 0; r < PROJ_ROWS; r++)
        out[(size_t)(r0 + r) * 96 + t] = acc[r];
}

// ---------------- sampling: softmax + bilinear gather + point aggregation ----------------
// writes attn pre-rounded to tf32 bit patterns (consumed by GEMM2)
__global__ __launch_bounds__(384)
void sample_kernel(const float* __restrict__ v,       // g_v [B,L,D] fp32
                   const float* __restrict__ offwt,   // [M,96]
                   float* __restrict__ attn) {        // [B,L,D] tf32 patterns
    __shared__ float row[96];
    __shared__ float sw[NH_][NP_];
    __shared__ int   sidx[NH_][NP_][4];
    __shared__ float swg[NH_][NP_][4];

    const int bl = blockIdx.x;           // 0..32767
    const int b = bl >> 12;
    const int l = bl & (L_ - 1);
    const int t = threadIdx.x;

    if (t < 96) row[t] = offwt[(size_t)bl * 96 + t];
    __syncthreads();

    if (t < NH_) {
        float lg[NP_];
        float m = -1e30f;
        #pragma unroll
        for (int p = 0; p < NP_; p++) { lg[p] = row[64 + t * NP_ + p]; m = fmaxf(m, lg[p]); }
        float s = 0.f;
        #pragma unroll
        for (int p = 0; p < NP_; p++) { lg[p] = __expf(lg[p] - m); s += lg[p]; }
        float inv = 1.f / s;
        #pragma unroll
        for (int p = 0; p < NP_; p++) sw[t][p] = lg[p] * inv;
    }
    __syncthreads();

    if (t < NH_ * NP_) {
        const int hh = t >> 2, p = t & 3;
        const float off0 = row[hh * (NP_ * 2) + p * 2 + 0];
        const float off1 = row[hh * (NP_ * 2) + p * 2 + 1];
        const float gx = (float)(l & (GRID_ - 1)) * (1.f / (GRID_ - 1));
        const float gy = (float)(l >> 6)          * (1.f / (GRID_ - 1));
        const float ph = fminf(fmaxf(gx + off0, 0.f), 1.f) * (float)(GRID_ - 1);
        const float pw = fminf(fmaxf(gy + off1, 0.f), 1.f) * (float)(GRID_ - 1);
        const float y0f = floorf(ph), x0f = floorf(pw);
        const float wy = ph - y0f,    wx = pw - x0f;
        const int y0 = (int)y0f, x0 = (int)x0f;
        const int y1 = min(y0 + 1, GRID_ - 1);
        const int x1 = min(x0 + 1, GRID_ - 1);
        const float s = sw[hh][p];
        sidx[hh][p][0] = y0 * GRID_ + x0;  swg[hh][p][0] = s * (1.f - wy) * (1.f - wx);
        sidx[hh][p][1] = y0 * GRID_ + x1;  swg[hh][p][1] = s * (1.f - wy) * wx;
        sidx[hh][p][2] = y1 * GRID_ + x0;  swg[hh][p][2] = s * wy * (1.f - wx);
        sidx[hh][p][3] = y1 * GRID_ + x1;  swg[hh][p][3] = s * wy * wx;
    }
    __syncthreads();

    const int hh = t / HD_;
    const int dh = t % HD_;
    const float* vb = v + (size_t)b * L_ * D_ + hh * HD_ + dh;

    float acc = 0.f;
    #pragma unroll
    for (int p = 0; p < NP_; p++) {
        #pragma unroll
        for (int c = 0; c < 4; c++) {
            acc += swg[hh][p][c] * vb[(size_t)sidx[hh][p][c] * D_];
        }
    }
    attn[(size_t)bl * D_ + t] = __uint_as_float(f2tf32(acc));
}

// ---------------- launch ----------------
extern "C" void kernel_launch(void* const* d_in, const int* in_sizes, int n_in,
                              void* d_out, int out_size) {
    const float* query = (const float*)d_in[0];
    // d_in[1] = key (dead)
    const float* value = (const float*)d_in[2];
    // d_in[3..6] = Wq, bq, Wk, bk (dead)
    const float* Wv   = (const float*)d_in[7];
    const float* bv   = (const float*)d_in[8];
    const float* Woff = (const float*)d_in[9];
    const float* boff = (const float*)d_in[10];
    const float* Wwt  = (const float*)d_in[11];
    const float* bwt  = (const float*)d_in[12];
    const float* Wo   = (const float*)d_in[13];
    const float* bo   = (const float*)d_in[14];
    float* out = (float*)d_out;

    float *gv, *gow, *gat, *gac, *gwv, *gwo;
    cudaGetSymbolAddress((void**)&gv,  g_v);
    cudaGetSymbolAddress((void**)&gow, g_offwt);
    cudaGetSymbolAddress((void**)&gat, g_attn);
    cudaGetSymbolAddress((void**)&gac, g_acvt);
    cudaGetSymbolAddress((void**)&gwv, g_wv32);
    cudaGetSymbolAddress((void**)&gwo, g_wo32);

    cudaFuncSetAttribute(gemm_tf32_kernel,
                         cudaFuncAttributeMaxDynamicSharedMemorySize,
                         GEMM_SMEM_BYTES);

    // 0) tf32 conversion pre-passes
    cvt_tf32_kernel<<<1024, 256>>>((const float4*)value, (float4*)gac, (M_ * D_) / 4);
    cvt_tf32_kernel<<<72, 256>>>((const float4*)Wv, (float4*)gwv, (D_ * D_) / 4);
    cvt_tf32_kernel<<<72, 256>>>((const float4*)Wo, (float4*)gwo, (D_ * D_) / 4);

    // 1) v = value @ Wv + bv   (tf32 tensor cores, fp32 accumulate)
    {
        dim3 grid(D_ / BN_, M_ / BM_);
        gemm_tf32_kernel<<<grid, 256, GEMM_SMEM_BYTES>>>(gac, gwv, bv, gv, M_, D_, D_);
    }
    // 2) off/wt projection (exact fp32 — offsets are x63 error-amplified)
    proj_offwt_kernel<<<M_ / PROJ_ROWS, 96>>>(query, Woff, boff, Wwt, bwt, gow);
    // 3) softmax + bilinear sampling + aggregation (writes tf32-rounded attn)
    sample_kernel<<<M_, 384>>>(gv, gow, gat);
    // 4) out = attn @ Wo + bo
    {
        dim3 grid(D_ / BN_, M_ / BM_);
        gemm_tf32_kernel<<<grid, 256, GEMM_SMEM_BYTES>>>(gat, gwo, bo, out, M_, D_, D_);
    }
}

// round 4
// speedup vs baseline: 2.6992x; 1.2547x over previous
#include <cuda_runtime.h>
#include <cuda_bf16.h>
#include <math.h>
#include <stdint.h>

// Problem constants (fixed shapes from reference setup_inputs)
#define B_  8
#define L_  4096
#define D_  384
#define NH_ 8
#define NP_ 4
#define HD_ 48           // D_/NH_
#define GRID_ 64         // h = w = sqrt(L_) = 64
#define M_  (B_ * L_)    // 32768 rows

// ---------------- scratch (no cudaMalloc allowed) ----------------
__device__ float g_v[(size_t)M_ * D_];        // value @ Wv + bv (fp32)
__device__ float g_offwt[(size_t)M_ * 96];    // [off(64) | wt(32)] fp32 (near-exact)
__device__ float g_attn[(size_t)M_ * D_];     // sampled, tf32-rounded bit patterns
__device__ float g_acvt[(size_t)M_ * D_];     // value tf32-rounded
__device__ float g_wv32[D_ * D_];             // Wv tf32-rounded
__device__ float g_wo32[D_ * D_];             // Wo tf32-rounded
__device__ float g_wpk_hi[D_ * 96];           // packed [Woff|Wwt] tf32 hi
__device__ float g_wpk_lo[D_ * 96];           // packed [Woff|Wwt] tf32 lo (residual)
__device__ float g_bpk[96];                   // packed [boff|bwt]

__device__ __forceinline__ uint32_t f2tf32(float f) {
    uint32_t u;
    asm("cvt.rna.tf32.f32 %0, %1;" : "=r"(u) : "f"(f));
    return u;
}

// ---------------- tf32 conversion pre-pass (float4 streaming) ----------------
__global__ __launch_bounds__(256)
void cvt_tf32_kernel(const float4* __restrict__ in, float4* __restrict__ out, int n4) {
    int i = blockIdx.x * blockDim.x + threadIdx.x;
    int stride = gridDim.x * blockDim.x;
    for (; i < n4; i += stride) {
        float4 v = in[i];
        float4 o;
        o.x = __uint_as_float(f2tf32(v.x));
        o.y = __uint_as_float(f2tf32(v.y));
        o.z = __uint_as_float(f2tf32(v.z));
        o.w = __uint_as_float(f2tf32(v.w));
        out[i] = o;
    }
}

// ---------------- pack [Woff|Wwt] -> hi/lo tf32 split + bias pack ----------------
__global__ __launch_bounds__(256)
void pack_projw_kernel(const float* __restrict__ Woff, const float* __restrict__ boff,
                       const float* __restrict__ Wwt,  const float* __restrict__ bwt,
                       float* __restrict__ whi, float* __restrict__ wlo,
                       float* __restrict__ bpk) {
    int i = blockIdx.x * blockDim.x + threadIdx.x;
    int total = D_ * 96;
    for (; i < total; i += gridDim.x * blockDim.x) {
        int k = i / 96, c = i % 96;
        float w = (c < 64) ? Woff[k * 64 + c] : Wwt[k * 32 + (c - 64)];
        uint32_t h = f2tf32(w);
        float r = w - __uint_as_float(h);
        whi[i] = __uint_as_float(h);
        wlo[i] = __uint_as_float(f2tf32(r));
    }
    if (blockIdx.x == 0 && threadIdx.x < 96) {
        int c = threadIdx.x;
        bpk[c] = (c < 64) ? boff[c] : bwt[c - 64];
    }
}

// =====================================================================
// MMA + cp.async helpers
// =====================================================================
__device__ __forceinline__ void cp_async16(uint32_t saddr, const void* gptr) {
    asm volatile("cp.async.cg.shared.global [%0], [%1], 16;\n" :: "r"(saddr), "l"(gptr));
}
__device__ __forceinline__ void cp_commit() {
    asm volatile("cp.async.commit_group;\n" ::: "memory");
}
template <int N>
__device__ __forceinline__ void cp_wait() {
    asm volatile("cp.async.wait_group %0;\n" :: "n"(N) : "memory");
}

__device__ __forceinline__ void mma_tf32(float c[4], uint32_t a0, uint32_t a1,
                                         uint32_t a2, uint32_t a3,
                                         uint32_t b0, uint32_t b1) {
    asm volatile(
        "mma.sync.aligned.m16n8k8.row.col.f32.tf32.tf32.f32 "
        "{%0,%1,%2,%3}, {%4,%5,%6,%7}, {%8,%9}, {%0,%1,%2,%3};"
        : "+f"(c[0]), "+f"(c[1]), "+f"(c[2]), "+f"(c[3])
        : "r"(a0), "r"(a1), "r"(a2), "r"(a3), "r"(b0), "r"(b1));
}

// =====================================================================
// TF32 tensor-core GEMM, 3-stage cp.async pipeline, ONE sync per iter.
// C[M,N] = A[M,K] @ W[K,N] + bias[N]. A, W already tf32 bit patterns.
// BM=128, BN=128, BK=32, 256 threads (8 warps 2x4), warp tile 64x32.
// =====================================================================
#define BM_ 128
#define BN_ 128
#define BK_ 32
#define ASTR 36               // A smem row stride (words)
#define BSTR 136              // B smem row stride (words)
#define A_WORDS (BM_ * ASTR)  // 4608
#define B_WORDS (BK_ * BSTR)  // 4352
#define STAGE_WORDS (A_WORDS + B_WORDS)   // 8960 words = 35840 B
#define NSTAGE 3
#define GEMM_SMEM_BYTES (NSTAGE * STAGE_WORDS * 4)
#define NK_ITERS (D_ / BK_)   // 12

__global__ __launch_bounds__(256, 2)
void gemm_tf32_kernel(const float* __restrict__ A,
                      const float* __restrict__ W,
                      const float* __restrict__ bias,
                      float* __restrict__ C,
                      int M, int N, int K) {
    extern __shared__ uint32_t smem[];   // [NSTAGE][STAGE_WORDS]

    const int tid  = threadIdx.x;
    const int lane = tid & 31;
    const int warp = tid >> 5;
    const int m0 = blockIdx.y * BM_;
    const int n0 = blockIdx.x * BN_;

    const int warp_m = warp >> 2;      // 0..1
    const int warp_n = warp & 3;       // 0..3
    const int mBase = warp_m * 64;
    const int nBase = warp_n * 32;
    const int qr = lane >> 2;          // 0..7
    const int qc = lane & 3;           // 0..3

    uint32_t smem_u32 = (uint32_t)__cvta_generic_to_shared((void*)smem);

    const int aRow0 = tid >> 3;           // 0..31 (+32*i)
    const int aC16  = (tid & 7) * 16;
    const int bRow0 = tid >> 5;           // 0..7 (+8*i)
    const int bC16  = (tid & 31) * 16;

    float acc[4][4][4];
    #pragma unroll
    for (int i = 0; i < 4; i++)
        #pragma unroll
        for (int j = 0; j < 4; j++)
            #pragma unroll
            for (int r = 0; r < 4; r++) acc[i][j][r] = 0.f;

    auto stage = [&](int k0, int buf) {
        uint32_t base = smem_u32 + buf * (STAGE_WORDS * 4);
        #pragma unroll
        for (int i = 0; i < 4; i++) {
            int arow = aRow0 + i * 32;
            cp_async16(base + arow * (ASTR * 4) + aC16,
                       A + (size_t)(m0 + arow) * K + k0 + (aC16 >> 2));
            int brow = bRow0 + i * 8;
            cp_async16(base + (A_WORDS * 4) + brow * (BSTR * 4) + bC16,
                       W + (size_t)(k0 + brow) * N + n0 + (bC16 >> 2));
        }
    };

    stage(0, 0); cp_commit();
    stage(BK_, 1); cp_commit();

    int buf = 0;
    for (int it = 0; it < NK_ITERS; it++) {
        cp_wait<1>();
        __syncthreads();

        if (it + 2 < NK_ITERS) {
            int nb = buf + 2; if (nb >= NSTAGE) nb -= NSTAGE;
            stage((it + 2) * BK_, nb);
        }
        cp_commit();   // commit (possibly empty) group to keep counts aligned

        const uint32_t* As = smem + buf * STAGE_WORDS;
        const uint32_t* Bs = As + A_WORDS;

        #pragma unroll
        for (int ks = 0; ks < 4; ks++) {
            const int kk = ks * 8;
            uint32_t b0[4], b1[4];
            #pragma unroll
            for (int nt = 0; nt < 4; nt++) {
                int col = nBase + nt * 8 + qr;
                b0[nt] = Bs[(kk + qc) * BSTR + col];
                b1[nt] = Bs[(kk + qc + 4) * BSTR + col];
            }
            #pragma unroll
            for (int mt = 0; mt < 4; mt++) {
                int row = mBase + mt * 16 + qr;
                int i00 = row * ASTR + kk + qc;
                int i10 = (row + 8) * ASTR + kk + qc;
                uint32_t a0 = As[i00], a1 = As[i10];
                uint32_t a2 = As[i00 + 4], a3 = As[i10 + 4];
                #pragma unroll
                for (int nt = 0; nt < 4; nt++) {
                    mma_tf32(acc[mt][nt], a0, a1, a2, a3, b0[nt], b1[nt]);
                }
            }
        }
        buf++; if (buf >= NSTAGE) buf = 0;
    }

    #pragma unroll
    for (int mt = 0; mt < 4; mt++) {
        int r0 = m0 + mBase + mt * 16 + qr;
        int r1 = r0 + 8;
        #pragma unroll
        for (int nt = 0; nt < 4; nt++) {
            int c0 = n0 + nBase + nt * 8 + 2 * qc;
            float bb0 = bias[c0], bb1 = bias[c0 + 1];
            float2 o0 = make_float2(acc[mt][nt][0] + bb0, acc[mt][nt][1] + bb1);
            float2 o1 = make_float2(acc[mt][nt][2] + bb0, acc[mt][nt][3] + bb1);
            *reinterpret_cast<float2*>(C + (size_t)r0 * N + c0) = o0;
            *reinterpret_cast<float2*>(C + (size_t)r1 * N + c0) = o1;
        }
    }
}

// =====================================================================
// proj GEMM, 3xTF32 (near-fp32): offwt[M,96] = query[M,384] @ Wpk + bpk
// BM=128, BN=96, BK=32, 256 threads (8 warps 2x4), warp tile 64x24.
// A split hi/lo at STS time; W pre-split in gmem. Register double-buffer.
// =====================================================================
#define PJ_ASTR 36
#define PJ_BSTR 100
#define PJ_A_WORDS (BM_ * PJ_ASTR)       // 4608 per (hi|lo)
#define PJ_B_WORDS (BK_ * PJ_BSTR)       // 3200 per (hi|lo)
#define PJ_SMEM_WORDS (2 * PJ_A_WORDS + 2 * PJ_B_WORDS)  // 15616 words
#define PJ_SMEM_BYTES (PJ_SMEM_WORDS * 4)                // 62464 B

__global__ __launch_bounds__(256, 2)
void proj_gemm3x_kernel(const float* __restrict__ A,      // query fp32
                        const float* __restrict__ Whi,    // [384][96] tf32 hi
                        const float* __restrict__ Wlo,    // [384][96] tf32 lo
                        const float* __restrict__ bias,   // [96]
                        float* __restrict__ C) {          // [M][96]
    extern __shared__ uint32_t smem[];
    uint32_t* Ahi = smem;
    uint32_t* Alo = smem + PJ_A_WORDS;
    uint32_t* Bhi = smem + 2 * PJ_A_WORDS;
    uint32_t* Blo = smem + 2 * PJ_A_WORDS + PJ_B_WORDS;

    const int tid  = threadIdx.x;
    const int lane = tid & 31;
    const int warp = tid >> 5;
    const int m0 = blockIdx.x * BM_;

    const int warp_m = warp >> 2;      // 0..1
    const int warp_n = warp & 3;       // 0..3
    const int mBase = warp_m * 64;
    const int nBase = warp_n * 24;
    const int qr = lane >> 2;
    const int qc = lane & 3;

    // staging coords: A 128x32 = 1024 float4, 4/thread; B(hi,lo) 32x96 = 768 float4 each, 3/thread
    const int aRow0 = tid >> 3;
    const int aC4   = (tid & 7) * 4;
    const int bRow0 = tid / 24;          // 768 chunks: idx/24 gives row (24 float4 per row)
    const int bC4   = (tid % 24) * 4;

    float4 aReg[4];
    float4 bhReg[3], blReg[3];

    auto gload = [&](int k0) {
        #pragma unroll
        for (int i = 0; i < 4; i++) {
            int arow = aRow0 + i * 32;
            aReg[i] = *reinterpret_cast<const float4*>(A + (size_t)(m0 + arow) * D_ + k0 + aC4);
        }
        #pragma unroll
        for (int i = 0; i < 3; i++) {
            int idx = tid + i * 256;
            int brow = idx / 24;
            int bc4  = (idx % 24) * 4;
            bhReg[i] = *reinterpret_cast<const float4*>(Whi + (size_t)(k0 + brow) * 96 + bc4);
            blReg[i] = *reinterpret_cast<const float4*>(Wlo + (size_t)(k0 + brow) * 96 + bc4);
        }
    };
    auto sstore = [&]() {
        #pragma unroll
        for (int i = 0; i < 4; i++) {
            int arow = aRow0 + i * 32;
            uint32_t* ph = Ahi + arow * PJ_ASTR + aC4;
            uint32_t* pl = Alo + arow * PJ_ASTR + aC4;
            float vv[4] = {aReg[i].x, aReg[i].y, aReg[i].z, aReg[i].w};
            #pragma unroll
            for (int j = 0; j < 4; j++) {
                uint32_t h = f2tf32(vv[j]);
                float r = vv[j] - __uint_as_float(h);
                ph[j] = h;
                pl[j] = f2tf32(r);
            }
        }
        #pragma unroll
        for (int i = 0; i < 3; i++) {
            int idx = tid + i * 256;
            int brow = idx / 24;
            int bc4  = (idx % 24) * 4;
            *reinterpret_cast<float4*>(&Bhi[brow * PJ_BSTR + bc4]) = bhReg[i];
            *reinterpret_cast<float4*>(&Blo[brow * PJ_BSTR + bc4]) = blReg[i];
        }
    };

    float acc[4][3][4];
    #pragma unroll
    for (int i = 0; i < 4; i++)
        #pragma unroll
        for (int j = 0; j < 3; j++)
            #pragma unroll
            for (int r = 0; r < 4; r++) acc[i][j][r] = 0.f;

    gload(0);

    for (int it = 0; it < NK_ITERS; it++) {
        sstore();
        __syncthreads();
        if (it + 1 < NK_ITERS) gload((it + 1) * BK_);

        #pragma unroll
        for (int ks = 0; ks < 4; ks++) {
            const int kk = ks * 8;
            uint32_t bh0[3], bh1[3], bl0[3], bl1[3];
            #pragma unroll
            for (int nt = 0; nt < 3; nt++) {
                int col = nBase + nt * 8 + qr;
                bh0[nt] = Bhi[(kk + qc) * PJ_BSTR + col];
                bh1[nt] = Bhi[(kk + qc + 4) * PJ_BSTR + col];
                bl0[nt] = Blo[(kk + qc) * PJ_BSTR + col];
                bl1[nt] = Blo[(kk + qc + 4) * PJ_BSTR + col];
            }
            #pragma unroll
            for (int mt = 0; mt < 4; mt++) {
                int row = mBase + mt * 16 + qr;
                int i00 = row * PJ_ASTR + kk + qc;
                int i10 = (row + 8) * PJ_ASTR + kk + qc;
                uint32_t ah0 = Ahi[i00], ah1 = Ahi[i10];
                uint32_t ah2 = Ahi[i00 + 4], ah3 = Ahi[i10 + 4];
                uint32_t al0 = Alo[i00], al1 = Alo[i10];
                uint32_t al2 = Alo[i00 + 4], al3 = Alo[i10 + 4];
                #pragma unroll
                for (int nt = 0; nt < 3; nt++) {
                    mma_tf32(acc[mt][nt], ah0, ah1, ah2, ah3, bl0[nt], bl1[nt]);
                    mma_tf32(acc[mt][nt], al0, al1, al2, al3, bh0[nt], bh1[nt]);
                    mma_tf32(acc[mt][nt], ah0, ah1, ah2, ah3, bh0[nt], bh1[nt]);
                }
            }
        }
        __syncthreads();
    }

    #pragma unroll
    for (int mt = 0; mt < 4; mt++) {
        int r0 = m0 + mBase + mt * 16 + qr;
        int r1 = r0 + 8;
        #pragma unroll
        for (int nt = 0; nt < 3; nt++) {
            int c0 = nBase + nt * 8 + 2 * qc;
            float bb0 = bias[c0], bb1 = bias[c0 + 1];
            float2 o0 = make_float2(acc[mt][nt][0] + bb0, acc[mt][nt][1] + bb1);
            float2 o1 = make_float2(acc[mt][nt][2] + bb0, acc[mt][nt][3] + bb1);
            *reinterpret_cast<float2*>(C + (size_t)r0 * 96 + c0) = o0;
            *reinterpret_cast<float2*>(C + (size_t)r1 * 96 + c0) = o1;
        }
    }
}

// ---------------- sampling: softmax + bilinear gather + point aggregation ----------------
__global__ __launch_bounds__(384)
void sample_kernel(const float* __restrict__ v,       // g_v [B,L,D] fp32
                   const float* __restrict__ offwt,   // [M,96]
                   float* __restrict__ attn) {        // [B,L,D] tf32 patterns
    __shared__ float row[96];
    __shared__ float sw[NH_][NP_];
    __shared__ int   sidx[NH_][NP_][4];
    __shared__ float swg[NH_][NP_][4];

    const int bl = blockIdx.x;
    const int b = bl >> 12;
    const int l = bl & (L_ - 1);
    const int t = threadIdx.x;

    if (t < 96) row[t] = offwt[(size_t)bl * 96 + t];
    __syncthreads();

    if (t < NH_) {
        float lg[NP_];
        float m = -1e30f;
        #pragma unroll
        for (int p = 0; p < NP_; p++) { lg[p] = row[64 + t * NP_ + p]; m = fmaxf(m, lg[p]); }
        float s = 0.f;
        #pragma unroll
        for (int p = 0; p < NP_; p++) { lg[p] = __expf(lg[p] - m); s += lg[p]; }
        float inv = 1.f / s;
        #pragma unroll
        for (int p = 0; p < NP_; p++) sw[t][p] = lg[p] * inv;
    }
    __syncthreads();

    if (t < NH_ * NP_) {
        const int hh = t >> 2, p = t & 3;
        const float off0 = row[hh * (NP_ * 2) + p * 2 + 0];
        const float off1 = row[hh * (NP_ * 2) + p * 2 + 1];
        const float gx = (float)(l & (GRID_ - 1)) * (1.f / (GRID_ - 1));
        const float gy = (float)(l >> 6)          * (1.f / (GRID_ - 1));
        const float ph = fminf(fmaxf(gx + off0, 0.f), 1.f) * (float)(GRID_ - 1);
        const float pw = fminf(fmaxf(gy + off1, 0.f), 1.f) * (float)(GRID_ - 1);
        const float y0f = floorf(ph), x0f = floorf(pw);
        const float wy = ph - y0f,    wx = pw - x0f;
        const int y0 = (int)y0f, x0 = (int)x0f;
        const int y1 = min(y0 + 1, GRID_ - 1);
        const int x1 = min(x0 + 1, GRID_ - 1);
        const float s = sw[hh][p];
        sidx[hh][p][0] = y0 * GRID_ + x0;  swg[hh][p][0] = s * (1.f - wy) * (1.f - wx);
        sidx[hh][p][1] = y0 * GRID_ + x1;  swg[hh][p][1] = s * (1.f - wy) * wx;
        sidx[hh][p][2] = y1 * GRID_ + x0;  swg[hh][p][2] = s * wy * (1.f - wx);
        sidx[hh][p][3] = y1 * GRID_ + x1;  swg[hh][p][3] = s * wy * wx;
    }
    __syncthreads();

    const int hh = t / HD_;
    const int dh = t % HD_;
    const float* vb = v + (size_t)b * L_ * D_ + hh * HD_ + dh;

    float acc = 0.f;
    #pragma unroll
    for (int p = 0; p < NP_; p++) {
        #pragma unroll
        for (int c = 0; c < 4; c++) {
            acc += swg[hh][p][c] * vb[(size_t)sidx[hh][p][c] * D_];
        }
    }
    attn[(size_t)bl * D_ + t] = __uint_as_float(f2tf32(acc));
}

// ---------------- launch ----------------
extern "C" void kernel_launch(void* const* d_in, const int* in_sizes, int n_in,
                              void* d_out, int out_size) {
    const float* query = (const float*)d_in[0];
    const float* value = (const float*)d_in[2];
    const float* Wv   = (const float*)d_in[7];
    const float* bv   = (const float*)d_in[8];
    const float* Woff = (const float*)d_in[9];
    const float* boff = (const float*)d_in[10];
    const float* Wwt  = (const float*)d_in[11];
    const float* bwt  = (const float*)d_in[12];
    const float* Wo   = (const float*)d_in[13];
    const float* bo   = (const float*)d_in[14];
    float* out = (float*)d_out;

    float *gv, *gow, *gat, *gac, *gwv, *gwo, *gwh, *gwl, *gbp;
    cudaGetSymbolAddress((void**)&gv,  g_v);
    cudaGetSymbolAddress((void**)&gow, g_offwt);
    cudaGetSymbolAddress((void**)&gat, g_attn);
    cudaGetSymbolAddress((void**)&gac, g_acvt);
    cudaGetSymbolAddress((void**)&gwv, g_wv32);
    cudaGetSymbolAddress((void**)&gwo, g_wo32);
    cudaGetSymbolAddress((void**)&gwh, g_wpk_hi);
    cudaGetSymbolAddress((void**)&gwl, g_wpk_lo);
    cudaGetSymbolAddress((void**)&gbp, g_bpk);

    cudaFuncSetAttribute(gemm_tf32_kernel,
                         cudaFuncAttributeMaxDynamicSharedMemorySize, GEMM_SMEM_BYTES);
    cudaFuncSetAttribute(proj_gemm3x_kernel,
                         cudaFuncAttributeMaxDynamicSharedMemorySize, PJ_SMEM_BYTES);

    // 0) prep: tf32 conversions + proj weight pack/split
    cvt_tf32_kernel<<<1024, 256>>>((const float4*)value, (float4*)gac, (M_ * D_) / 4);
    cvt_tf32_kernel<<<72, 256>>>((const float4*)Wv, (float4*)gwv, (D_ * D_) / 4);
    cvt_tf32_kernel<<<72, 256>>>((const float4*)Wo, (float4*)gwo, (D_ * D_) / 4);
    pack_projw_kernel<<<144, 256>>>(Woff, boff, Wwt, bwt, gwh, gwl, gbp);

    // 1) offwt = query @ [Woff|Wwt] + [boff|bwt]   (3xTF32 tensor, ~fp32 accurate)
    proj_gemm3x_kernel<<<M_ / BM_, 256, PJ_SMEM_BYTES>>>(query, gwh, gwl, gbp, gow);

    // 2) v = value @ Wv + bv   (single tf32)
    {
        dim3 grid(D_ / BN_, M_ / BM_);
        gemm_tf32_kernel<<<grid, 256, GEMM_SMEM_BYTES>>>(gac, gwv, bv, gv, M_, D_, D_);
    }
    // 3) softmax + bilinear sampling + aggregation (writes tf32-rounded attn)
    sample_kernel<<<M_, 384>>>(gv, gow, gat);
    // 4) out = attn @ Wo + bo   (single tf32)
    {
        dim3 grid(D_ / BN_, M_ / BM_);
        gemm_tf32_kernel<<<grid, 256, GEMM_SMEM_BYTES>>>(gat, gwo, bo, out, M_, D_, D_);
    }
}

// round 5
// speedup vs baseline: 3.3454x; 1.2394x over previous
#include <cuda_runtime.h>
#include <cuda_bf16.h>
#include <math.h>
#include <stdint.h>

// Problem constants (fixed shapes from reference setup_inputs)
#define B_  8
#define L_  4096
#define D_  384
#define NH_ 8
#define NP_ 4
#define HD_ 48           // D_/NH_
#define GRID_ 64         // h = w = sqrt(L_) = 64
#define M_  (B_ * L_)    // 32768 rows

// ---------------- scratch (no cudaMalloc allowed) ----------------
__device__ float g_v[(size_t)M_ * D_];        // value @ Wv + bv (fp32)
__device__ float g_offwt[(size_t)M_ * 96];    // [off(64) | wt(32)] fp32 (near-exact)
__device__ float g_attn[(size_t)M_ * D_];     // sampled, tf32-rounded bit patterns
__device__ float g_wv32[D_ * D_];             // Wv tf32-rounded
__device__ float g_wo32[D_ * D_];             // Wo tf32-rounded
__device__ float g_wpk_hi[D_ * 96];           // packed [Woff|Wwt] tf32 hi
__device__ float g_wpk_lo[D_ * 96];           // packed [Woff|Wwt] tf32 lo (residual)
__device__ float g_bpk[96];                   // packed [boff|bwt]

__device__ __forceinline__ uint32_t f2tf32(float f) {
    uint32_t u;
    asm("cvt.rna.tf32.f32 %0, %1;" : "=r"(u) : "f"(f));
    return u;
}

// ---------------- tf32 conversion pre-pass (float4 streaming) ----------------
__global__ __launch_bounds__(256)
void cvt_tf32_kernel(const float4* __restrict__ in, float4* __restrict__ out, int n4) {
    int i = blockIdx.x * blockDim.x + threadIdx.x;
    int stride = gridDim.x * blockDim.x;
    for (; i < n4; i += stride) {
        float4 v = in[i];
        float4 o;
        o.x = __uint_as_float(f2tf32(v.x));
        o.y = __uint_as_float(f2tf32(v.y));
        o.z = __uint_as_float(f2tf32(v.z));
        o.w = __uint_as_float(f2tf32(v.w));
        out[i] = o;
    }
}

// ---------------- pack [Woff|Wwt] -> hi/lo tf32 split + bias pack ----------------
__global__ __launch_bounds__(256)
void pack_projw_kernel(const float* __restrict__ Woff, const float* __restrict__ boff,
                       const float* __restrict__ Wwt,  const float* __restrict__ bwt,
                       float* __restrict__ whi, float* __restrict__ wlo,
                       float* __restrict__ bpk) {
    int i = blockIdx.x * blockDim.x + threadIdx.x;
    int total = D_ * 96;
    for (; i < total; i += gridDim.x * blockDim.x) {
        int k = i / 96, c = i % 96;
        float w = (c < 64) ? Woff[k * 64 + c] : Wwt[k * 32 + (c - 64)];
        uint32_t h = f2tf32(w);
        float r = w - __uint_as_float(h);
        whi[i] = __uint_as_float(h);
        wlo[i] = __uint_as_float(f2tf32(r));
    }
    if (blockIdx.x == 0 && threadIdx.x < 96) {
        int c = threadIdx.x;
        bpk[c] = (c < 64) ? boff[c] : bwt[c - 64];
    }
}

// =====================================================================
// MMA + cp.async helpers
// =====================================================================
__device__ __forceinline__ void cp_async16(uint32_t saddr, const void* gptr) {
    asm volatile("cp.async.cg.shared.global [%0], [%1], 16;\n" :: "r"(saddr), "l"(gptr));
}
__device__ __forceinline__ void cp_commit() {
    asm volatile("cp.async.commit_group;\n" ::: "memory");
}
template <int N>
__device__ __forceinline__ void cp_wait() {
    asm volatile("cp.async.wait_group %0;\n" :: "n"(N) : "memory");
}

__device__ __forceinline__ void mma_tf32(float c[4], uint32_t a0, uint32_t a1,
                                         uint32_t a2, uint32_t a3,
                                         uint32_t b0, uint32_t b1) {
    asm volatile(
        "mma.sync.aligned.m16n8k8.row.col.f32.tf32.tf32.f32 "
        "{%0,%1,%2,%3}, {%4,%5,%6,%7}, {%8,%9}, {%0,%1,%2,%3};"
        : "+f"(c[0]), "+f"(c[1]), "+f"(c[2]), "+f"(c[3])
        : "r"(a0), "r"(a1), "r"(a2), "r"(a3), "r"(b0), "r"(b1));
}

// =====================================================================
// Shared GEMM tile geometry
// =====================================================================
#define BM_ 128
#define BN_ 128
#define BK_ 32
#define ASTR 36               // A smem row stride (words)
#define BSTR 136              // B smem row stride (words)
#define A_WORDS (BM_ * ASTR)  // 4608
#define B_WORDS (BK_ * BSTR)  // 4352
#define STAGE_WORDS (A_WORDS + B_WORDS)   // 8960 words
#define NSTAGE 3
#define GEMM_SMEM_BYTES (NSTAGE * STAGE_WORDS * 4)
#define NK_ITERS (D_ / BK_)   // 12

// =====================================================================
// GEMM2: TF32 tensor-core GEMM, 3-stage cp.async, one sync per iter.
// A, W already tf32 bit patterns. (unchanged from R4)
// =====================================================================
__global__ __launch_bounds__(256, 2)
void gemm_tf32_kernel(const float* __restrict__ A,
                      const float* __restrict__ W,
                      const float* __restrict__ bias,
                      float* __restrict__ C,
                      int M, int N, int K) {
    extern __shared__ uint32_t smem[];   // [NSTAGE][STAGE_WORDS]

    const int tid  = threadIdx.x;
    const int lane = tid & 31;
    const int warp = tid >> 5;
    const int m0 = blockIdx.y * BM_;
    const int n0 = blockIdx.x * BN_;

    const int warp_m = warp >> 2;
    const int warp_n = warp & 3;
    const int mBase = warp_m * 64;
    const int nBase = warp_n * 32;
    const int qr = lane >> 2;
    const int qc = lane & 3;

    uint32_t smem_u32 = (uint32_t)__cvta_generic_to_shared((void*)smem);

    const int aRow0 = tid >> 3;
    const int aC16  = (tid & 7) * 16;
    const int bRow0 = tid >> 5;
    const int bC16  = (tid & 31) * 16;

    float acc[4][4][4];
    #pragma unroll
    for (int i = 0; i < 4; i++)
        #pragma unroll
        for (int j = 0; j < 4; j++)
            #pragma unroll
            for (int r = 0; r < 4; r++) acc[i][j][r] = 0.f;

    auto stage = [&](int k0, int buf) {
        uint32_t base = smem_u32 + buf * (STAGE_WORDS * 4);
        #pragma unroll
        for (int i = 0; i < 4; i++) {
            int arow = aRow0 + i * 32;
            cp_async16(base + arow * (ASTR * 4) + aC16,
                       A + (size_t)(m0 + arow) * K + k0 + (aC16 >> 2));
            int brow = bRow0 + i * 8;
            cp_async16(base + (A_WORDS * 4) + brow * (BSTR * 4) + bC16,
                       W + (size_t)(k0 + brow) * N + n0 + (bC16 >> 2));
        }
    };

    stage(0, 0); cp_commit();
    stage(BK_, 1); cp_commit();

    int buf = 0;
    for (int it = 0; it < NK_ITERS; it++) {
        cp_wait<1>();
        __syncthreads();

        if (it + 2 < NK_ITERS) {
            int nb = buf + 2; if (nb >= NSTAGE) nb -= NSTAGE;
            stage((it + 2) * BK_, nb);
        }
        cp_commit();

        const uint32_t* As = smem + buf * STAGE_WORDS;
        const uint32_t* Bs = As + A_WORDS;

        #pragma unroll
        for (int ks = 0; ks < 4; ks++) {
            const int kk = ks * 8;
            uint32_t b0[4], b1[4];
            #pragma unroll
            for (int nt = 0; nt < 4; nt++) {
                int col = nBase + nt * 8 + qr;
                b0[nt] = Bs[(kk + qc) * BSTR + col];
                b1[nt] = Bs[(kk + qc + 4) * BSTR + col];
            }
            #pragma unroll
            for (int mt = 0; mt < 4; mt++) {
                int row = mBase + mt * 16 + qr;
                int i00 = row * ASTR + kk + qc;
                int i10 = (row + 8) * ASTR + kk + qc;
                uint32_t a0 = As[i00], a1 = As[i10];
                uint32_t a2 = As[i00 + 4], a3 = As[i10 + 4];
                #pragma unroll
                for (int nt = 0; nt < 4; nt++) {
                    mma_tf32(acc[mt][nt], a0, a1, a2, a3, b0[nt], b1[nt]);
                }
            }
        }
        buf++; if (buf >= NSTAGE) buf = 0;
    }

    #pragma unroll
    for (int mt = 0; mt < 4; mt++) {
        int r0 = m0 + mBase + mt * 16 + qr;
        int r1 = r0 + 8;
        #pragma unroll
        for (int nt = 0; nt < 4; nt++) {
            int c0 = n0 + nBase + nt * 8 + 2 * qc;
            float bb0 = bias[c0], bb1 = bias[c0 + 1];
            float2 o0 = make_float2(acc[mt][nt][0] + bb0, acc[mt][nt][1] + bb1);
            float2 o1 = make_float2(acc[mt][nt][2] + bb0, acc[mt][nt][3] + bb1);
            *reinterpret_cast<float2*>(C + (size_t)r0 * N + c0) = o0;
            *reinterpret_cast<float2*>(C + (size_t)r1 * N + c0) = o1;
        }
    }
}

// =====================================================================
// GEMM1 (cvt-A): A raw fp32, converted to tf32 during LDG->STS staging
// (register double-buffer); B (pre-converted weights) via 3-stage cp.async.
// =====================================================================
#define CA_SMEM_WORDS (2 * A_WORDS + 3 * B_WORDS)   // 22272 words = 89088 B
#define CA_SMEM_BYTES (CA_SMEM_WORDS * 4)

__global__ __launch_bounds__(256, 2)
void gemm_cvtA_kernel(const float* __restrict__ A,   // raw fp32
                      const float* __restrict__ W,   // tf32 patterns
                      const float* __restrict__ bias,
                      float* __restrict__ C,
                      int M, int N, int K) {
    extern __shared__ uint32_t smem[];
    uint32_t* Asm = smem;                  // [2][A_WORDS]
    uint32_t* Bsm = smem + 2 * A_WORDS;    // [3][B_WORDS]

    const int tid  = threadIdx.x;
    const int lane = tid & 31;
    const int warp = tid >> 5;
    const int m0 = blockIdx.y * BM_;
    const int n0 = blockIdx.x * BN_;

    const int warp_m = warp >> 2;
    const int warp_n = warp & 3;
    const int mBase = warp_m * 64;
    const int nBase = warp_n * 32;
    const int qr = lane >> 2;
    const int qc = lane & 3;

    uint32_t smemB_u32 = (uint32_t)__cvta_generic_to_shared((void*)Bsm);

    const int aRow0 = tid >> 3;           // +32*i
    const int aC4   = (tid & 7) * 4;
    const int bRow0 = tid >> 5;           // +8*i
    const int bC16  = (tid & 31) * 16;

    float4 aReg[4];

    auto gloadA = [&](int k0) {
        #pragma unroll
        for (int i = 0; i < 4; i++) {
            int arow = aRow0 + i * 32;
            aReg[i] = *reinterpret_cast<const float4*>(A + (size_t)(m0 + arow) * K + k0 + aC4);
        }
    };
    auto sstoreA = [&](int buf) {
        uint32_t* dst = Asm + buf * A_WORDS;
        #pragma unroll
        for (int i = 0; i < 4; i++) {
            int arow = aRow0 + i * 32;
            uint32_t* p = dst + arow * ASTR + aC4;
            p[0] = f2tf32(aReg[i].x);
            p[1] = f2tf32(aReg[i].y);
            p[2] = f2tf32(aReg[i].z);
            p[3] = f2tf32(aReg[i].w);
        }
    };
    auto stageB = [&](int k0, int buf) {
        uint32_t base = smemB_u32 + buf * (B_WORDS * 4);
        #pragma unroll
        for (int i = 0; i < 4; i++) {
            int brow = bRow0 + i * 8;
            cp_async16(base + brow * (BSTR * 4) + bC16,
                       W + (size_t)(k0 + brow) * N + n0 + (bC16 >> 2));
        }
    };

    float acc[4][4][4];
    #pragma unroll
    for (int i = 0; i < 4; i++)
        #pragma unroll
        for (int j = 0; j < 4; j++)
            #pragma unroll
            for (int r = 0; r < 4; r++) acc[i][j][r] = 0.f;

    gloadA(0);
    stageB(0, 0); cp_commit();
    stageB(BK_, 1); cp_commit();

    int bufB = 0;
    for (int it = 0; it < NK_ITERS; it++) {
        sstoreA(it & 1);
        if (it + 1 < NK_ITERS) gloadA((it + 1) * BK_);

        cp_wait<1>();
        __syncthreads();

        if (it + 2 < NK_ITERS) {
            int nb = bufB + 2; if (nb >= 3) nb -= 3;
            stageB((it + 2) * BK_, nb);
        }
        cp_commit();

        const uint32_t* As = Asm + (it & 1) * A_WORDS;
        const uint32_t* Bs = Bsm + bufB * B_WORDS;

        #pragma unroll
        for (int ks = 0; ks < 4; ks++) {
            const int kk = ks * 8;
            uint32_t b0[4], b1[4];
            #pragma unroll
            for (int nt = 0; nt < 4; nt++) {
                int col = nBase + nt * 8 + qr;
                b0[nt] = Bs[(kk + qc) * BSTR + col];
                b1[nt] = Bs[(kk + qc + 4) * BSTR + col];
            }
            #pragma unroll
            for (int mt = 0; mt < 4; mt++) {
                int row = mBase + mt * 16 + qr;
                int i00 = row * ASTR + kk + qc;
                int i10 = (row + 8) * ASTR + kk + qc;
                uint32_t a0 = As[i00], a1 = As[i10];
                uint32_t a2 = As[i00 + 4], a3 = As[i10 + 4];
                #pragma unroll
                for (int nt = 0; nt < 4; nt++) {
                    mma_tf32(acc[mt][nt], a0, a1, a2, a3, b0[nt], b1[nt]);
                }
            }
        }
        bufB++; if (bufB >= 3) bufB = 0;
    }

    #pragma unroll
    for (int mt = 0; mt < 4; mt++) {
        int r0 = m0 + mBase + mt * 16 + qr;
        int r1 = r0 + 8;
        #pragma unroll
        for (int nt = 0; nt < 4; nt++) {
            int c0 = n0 + nBase + nt * 8 + 2 * qc;
            float bb0 = bias[c0], bb1 = bias[c0 + 1];
            float2 o0 = make_float2(acc[mt][nt][0] + bb0, acc[mt][nt][1] + bb1);
            float2 o1 = make_float2(acc[mt][nt][2] + bb0, acc[mt][nt][3] + bb1);
            *reinterpret_cast<float2*>(C + (size_t)r0 * N + c0) = o0;
            *reinterpret_cast<float2*>(C + (size_t)r1 * N + c0) = o1;
        }
    }
}

// =====================================================================
// proj GEMM, 3xTF32 (near-fp32): offwt[M,96] = query[M,384] @ Wpk + bpk
// (unchanged from R4)
// =====================================================================
#define PJ_ASTR 36
#define PJ_BSTR 100
#define PJ_A_WORDS (BM_ * PJ_ASTR)
#define PJ_B_WORDS (BK_ * PJ_BSTR)
#define PJ_SMEM_WORDS (2 * PJ_A_WORDS + 2 * PJ_B_WORDS)
#define PJ_SMEM_BYTES (PJ_SMEM_WORDS * 4)

__global__ __launch_bounds__(256, 2)
void proj_gemm3x_kernel(const float* __restrict__ A,
                        const float* __restrict__ Whi,
                        const float* __restrict__ Wlo,
                        const float* __restrict__ bias,
                        float* __restrict__ C) {
    extern __shared__ uint32_t smem[];
    uint32_t* Ahi = smem;
    uint32_t* Alo = smem + PJ_A_WORDS;
    uint32_t* Bhi = smem + 2 * PJ_A_WORDS;
    uint32_t* Blo = smem + 2 * PJ_A_WORDS + PJ_B_WORDS;

    const int tid  = threadIdx.x;
    const int lane = tid & 31;
    const int warp = tid >> 5;
    const int m0 = blockIdx.x * BM_;

    const int warp_m = warp >> 2;
    const int warp_n = warp & 3;
    const int mBase = warp_m * 64;
    const int nBase = warp_n * 24;
    const int qr = lane >> 2;
    const int qc = lane & 3;

    const int aRow0 = tid >> 3;
    const int aC4   = (tid & 7) * 4;

    float4 aReg[4];
    float4 bhReg[3], blReg[3];

    auto gload = [&](int k0) {
        #pragma unroll
        for (int i = 0; i < 4; i++) {
            int arow = aRow0 + i * 32;
            aReg[i] = *reinterpret_cast<const float4*>(A + (size_t)(m0 + arow) * D_ + k0 + aC4);
        }
        #pragma unroll
        for (int i = 0; i < 3; i++) {
            int idx = tid + i * 256;
            int brow = idx / 24;
            int bc4  = (idx % 24) * 4;
            bhReg[i] = *reinterpret_cast<const float4*>(Whi + (size_t)(k0 + brow) * 96 + bc4);
            blReg[i] = *reinterpret_cast<const float4*>(Wlo + (size_t)(k0 + brow) * 96 + bc4);
        }
    };
    auto sstore = [&]() {
        #pragma unroll
        for (int i = 0; i < 4; i++) {
            int arow = aRow0 + i * 32;
            uint32_t* ph = Ahi + arow * PJ_ASTR + aC4;
            uint32_t* pl = Alo + arow * PJ_ASTR + aC4;
            float vv[4] = {aReg[i].x, aReg[i].y, aReg[i].z, aReg[i].w};
            #pragma unroll
            for (int j = 0; j < 4; j++) {
                uint32_t h = f2tf32(vv[j]);
                float r = vv[j] - __uint_as_float(h);
                ph[j] = h;
                pl[j] = f2tf32(r);
            }
        }
        #pragma unroll
        for (int i = 0; i < 3; i++) {
            int idx = tid + i * 256;
            int brow = idx / 24;
            int bc4  = (idx % 24) * 4;
            *reinterpret_cast<float4*>(&Bhi[brow * PJ_BSTR + bc4]) = bhReg[i];
            *reinterpret_cast<float4*>(&Blo[brow * PJ_BSTR + bc4]) = blReg[i];
        }
    };

    float acc[4][3][4];
    #pragma unroll
    for (int i = 0; i < 4; i++)
        #pragma unroll
        for (int j = 0; j < 3; j++)
            #pragma unroll
            for (int r = 0; r < 4; r++) acc[i][j][r] = 0.f;

    gload(0);

    for (int it = 0; it < NK_ITERS; it++) {
        sstore();
        __syncthreads();
        if (it + 1 < NK_ITERS) gload((it + 1) * BK_);

        #pragma unroll
        for (int ks = 0; ks < 4; ks++) {
            const int kk = ks * 8;
            uint32_t bh0[3], bh1[3], bl0[3], bl1[3];
            #pragma unroll
            for (int nt = 0; nt < 3; nt++) {
                int col = nBase + nt * 8 + qr;
                bh0[nt] = Bhi[(kk + qc) * PJ_BSTR + col];
                bh1[nt] = Bhi[(kk + qc + 4) * PJ_BSTR + col];
                bl0[nt] = Blo[(kk + qc) * PJ_BSTR + col];
                bl1[nt] = Blo[(kk + qc + 4) * PJ_BSTR + col];
            }
            #pragma unroll
            for (int mt = 0; mt < 4; mt++) {
                int row = mBase + mt * 16 + qr;
                int i00 = row * PJ_ASTR + kk + qc;
                int i10 = (row + 8) * PJ_ASTR + kk + qc;
                uint32_t ah0 = Ahi[i00], ah1 = Ahi[i10];
                uint32_t ah2 = Ahi[i00 + 4], ah3 = Ahi[i10 + 4];
                uint32_t al0 = Alo[i00], al1 = Alo[i10];
                uint32_t al2 = Alo[i00 + 4], al3 = Alo[i10 + 4];
                #pragma unroll
                for (int nt = 0; nt < 3; nt++) {
                    mma_tf32(acc[mt][nt], ah0, ah1, ah2, ah3, bl0[nt], bl1[nt]);
                    mma_tf32(acc[mt][nt], al0, al1, al2, al3, bh0[nt], bh1[nt]);
                    mma_tf32(acc[mt][nt], ah0, ah1, ah2, ah3, bh0[nt], bh1[nt]);
                }
            }
        }
        __syncthreads();
    }

    #pragma unroll
    for (int mt = 0; mt < 4; mt++) {
        int r0 = m0 + mBase + mt * 16 + qr;
        int r1 = r0 + 8;
        #pragma unroll
        for (int nt = 0; nt < 3; nt++) {
            int c0 = nBase + nt * 8 + 2 * qc;
            float bb0 = bias[c0], bb1 = bias[c0 + 1];
            float2 o0 = make_float2(acc[mt][nt][0] + bb0, acc[mt][nt][1] + bb1);
            float2 o1 = make_float2(acc[mt][nt][2] + bb0, acc[mt][nt][3] + bb1);
            *reinterpret_cast<float2*>(C + (size_t)r0 * 96 + c0) = o0;
            *reinterpret_cast<float2*>(C + (size_t)r1 * 96 + c0) = o1;
        }
    }
}

// =====================================================================
// sampling: 4 rows per block, float4 gathers.
// thread t: r = t/96 (row in block), c4 = t%96 (float4 channel),
//           hh = c4/12 (head), d4 = c4%12 (float4 within head)
// =====================================================================
#define SROWS 4
__global__ __launch_bounds__(384)
void sample_kernel(const float* __restrict__ v,       // g_v [B,L,D] fp32
                   const float* __restrict__ offwt,   // [M,96]
                   float4* __restrict__ attn) {       // [B,L,D] tf32 patterns
    __shared__ float row[SROWS][96];
    __shared__ int   sidx[SROWS][NH_][NP_][4];
    __shared__ float swg[SROWS][NH_][NP_][4];

    const int bl0 = blockIdx.x * SROWS;
    const int b = bl0 >> 12;              // block never spans batch (4 | 4096)
    const int t = threadIdx.x;

    // load 4 offwt rows (384 floats)
    row[t / 96][t % 96] = offwt[(size_t)(bl0 + (t / 96)) * 96 + (t % 96)];
    __syncthreads();

    // setup: threads 0..127 -> (r, hh, p); softmax recomputed per point (cheap)
    if (t < SROWS * NH_ * NP_) {
        const int r  = t >> 5;
        const int hp = t & 31;
        const int hh = hp >> 2;
        const int p  = hp & 3;

        float lg[NP_];
        float m = -1e30f;
        #pragma unroll
        for (int q = 0; q < NP_; q++) { lg[q] = row[r][64 + hh * NP_ + q]; m = fmaxf(m, lg[q]); }
        float ssum = 0.f;
        #pragma unroll
        for (int q = 0; q < NP_; q++) ssum += __expf(lg[q] - m);
        const float s = __expf(lg[p] - m) / ssum;

        const int l = (bl0 + r) & (L_ - 1);
        const float off0 = row[r][hh * (NP_ * 2) + p * 2 + 0];
        const float off1 = row[r][hh * (NP_ * 2) + p * 2 + 1];
        const float gx = (float)(l & (GRID_ - 1)) * (1.f / (GRID_ - 1));
        const float gy = (float)(l >> 6)          * (1.f / (GRID_ - 1));
        const float ph = fminf(fmaxf(gx + off0, 0.f), 1.f) * (float)(GRID_ - 1);
        const float pw = fminf(fmaxf(gy + off1, 0.f), 1.f) * (float)(GRID_ - 1);
        const float y0f = floorf(ph), x0f = floorf(pw);
        const float wy = ph - y0f,    wx = pw - x0f;
        const int y0 = (int)y0f, x0 = (int)x0f;
        const int y1 = min(y0 + 1, GRID_ - 1);
        const int x1 = min(x0 + 1, GRID_ - 1);
        sidx[r][hh][p][0] = y0 * GRID_ + x0;  swg[r][hh][p][0] = s * (1.f - wy) * (1.f - wx);
        sidx[r][hh][p][1] = y0 * GRID_ + x1;  swg[r][hh][p][1] = s * (1.f - wy) * wx;
        sidx[r][hh][p][2] = y1 * GRID_ + x0;  swg[r][hh][p][2] = s * wy * (1.f - wx);
        sidx[r][hh][p][3] = y1 * GRID_ + x1;  swg[r][hh][p][3] = s * wy * wx;
    }
    __syncthreads();

    const int r  = t / 96;
    const int c4 = t % 96;
    const int hh = c4 / 12;
    const int d4 = c4 % 12;

    const float4* vb = reinterpret_cast<const float4*>(v) + (size_t)b * L_ * 96 + hh * 12 + d4;

    float4 acc = make_float4(0.f, 0.f, 0.f, 0.f);
    #pragma unroll
    for (int p = 0; p < NP_; p++) {
        #pragma unroll
        for (int c = 0; c < 4; c++) {
            const float w = swg[r][hh][p][c];
            const float4 vv = vb[(size_t)sidx[r][hh][p][c] * 96];
            acc.x += w * vv.x;
            acc.y += w * vv.y;
            acc.z += w * vv.z;
            acc.w += w * vv.w;
        }
    }
    float4 o;
    o.x = __uint_as_float(f2tf32(acc.x));
    o.y = __uint_as_float(f2tf32(acc.y));
    o.z = __uint_as_float(f2tf32(acc.z));
    o.w = __uint_as_float(f2tf32(acc.w));
    attn[(size_t)(bl0 + r) * 96 + c4] = o;
}

// ---------------- streams/events (host-side only; created pre-main) ----------------
struct AsyncCtx {
    cudaStream_t s1 = nullptr;
    cudaEvent_t evRoot = nullptr, ev1 = nullptr;
    AsyncCtx() {
        cudaStreamCreateWithFlags(&s1, cudaStreamNonBlocking);
        cudaEventCreateWithFlags(&evRoot, cudaEventDisableTiming);
        cudaEventCreateWithFlags(&ev1, cudaEventDisableTiming);
    }
};
static AsyncCtx g_async;

// ---------------- launch ----------------
extern "C" void kernel_launch(void* const* d_in, const int* in_sizes, int n_in,
                              void* d_out, int out_size) {
    const float* query = (const float*)d_in[0];
    const float* value = (const float*)d_in[2];
    const float* Wv   = (const float*)d_in[7];
    const float* bv   = (const float*)d_in[8];
    const float* Woff = (const float*)d_in[9];
    const float* boff = (const float*)d_in[10];
    const float* Wwt  = (const float*)d_in[11];
    const float* bwt  = (const float*)d_in[12];
    const float* Wo   = (const float*)d_in[13];
    const float* bo   = (const float*)d_in[14];
    float* out = (float*)d_out;

    float *gv, *gow, *gat, *gwv, *gwo, *gwh, *gwl, *gbp;
    cudaGetSymbolAddress((void**)&gv,  g_v);
    cudaGetSymbolAddress((void**)&gow, g_offwt);
    cudaGetSymbolAddress((void**)&gat, g_attn);
    cudaGetSymbolAddress((void**)&gwv, g_wv32);
    cudaGetSymbolAddress((void**)&gwo, g_wo32);
    cudaGetSymbolAddress((void**)&gwh, g_wpk_hi);
    cudaGetSymbolAddress((void**)&gwl, g_wpk_lo);
    cudaGetSymbolAddress((void**)&gbp, g_bpk);

    cudaFuncSetAttribute(gemm_tf32_kernel,
                         cudaFuncAttributeMaxDynamicSharedMemorySize, GEMM_SMEM_BYTES);
    cudaFuncSetAttribute(gemm_cvtA_kernel,
                         cudaFuncAttributeMaxDynamicSharedMemorySize, CA_SMEM_BYTES);
    cudaFuncSetAttribute(proj_gemm3x_kernel,
                         cudaFuncAttributeMaxDynamicSharedMemorySize, PJ_SMEM_BYTES);

    // ---- fork: side stream handles proj path + Wo cvt ----
    cudaEventRecord(g_async.evRoot, 0);
    cudaStreamWaitEvent(g_async.s1, g_async.evRoot, 0);

    pack_projw_kernel<<<144, 256, 0, g_async.s1>>>(Woff, boff, Wwt, bwt, gwh, gwl, gbp);
    proj_gemm3x_kernel<<<M_ / BM_, 256, PJ_SMEM_BYTES, g_async.s1>>>(query, gwh, gwl, gbp, gow);
    cvt_tf32_kernel<<<72, 256, 0, g_async.s1>>>((const float4*)Wo, (float4*)gwo, (D_ * D_) / 4);
    cudaEventRecord(g_async.ev1, g_async.s1);

    // ---- main stream: Wv cvt -> GEMM1 (A converted in-kernel) ----
    cvt_tf32_kernel<<<72, 256>>>((const float4*)Wv, (float4*)gwv, (D_ * D_) / 4);
    {
        dim3 grid(D_ / BN_, M_ / BM_);
        gemm_cvtA_kernel<<<grid, 256, CA_SMEM_BYTES>>>(value, gwv, bv, gv, M_, D_, D_);
    }

    // ---- join, then sample + GEMM2 ----
    cudaStreamWaitEvent(0, g_async.ev1, 0);
    sample_kernel<<<M_ / SROWS, 384>>>(gv, gow, (float4*)gat);
    {
        dim3 grid(D_ / BN_, M_ / BM_);
        gemm_tf32_kernel<<<grid, 256, GEMM_SMEM_BYTES>>>(gat, gwo, bo, out, M_, D_, D_);
    }
}